// round 4
// baseline (speedup 1.0000x reference)
#include <cuda_runtime.h>

#define SEQ   512
#define BATCH 2048
#define IND   4
#define H     50
#define BT    16                 // batch tile per CTA
#define NCTA  (BATCH / BT)       // 128
#define NTHR  672                // 21 warps
#define HP    52                 // padded hidden (mult of 4)
#define GP    17                 // gates row pad (conflict-free)

// Accurate fp32 activations: expf <=2ulp, IEEE division, tanhf <=2ulp.
__device__ __forceinline__ float sigf(float x) {
    return 1.0f / (1.0f + expf(-x));
}
__device__ __forceinline__ float tanh_acc(float x) {
    return tanhf(x);
}

__global__ __launch_bounds__(NTHR, 1)
void lstm_fused_kernel(
    const float* __restrict__ x,
    const float* __restrict__ w_ih1, const float* __restrict__ w_hh1,
    const float* __restrict__ b_ih1, const float* __restrict__ b_hh1,
    const float* __restrict__ w_ih2, const float* __restrict__ w_hh2,
    const float* __restrict__ b_ih2, const float* __restrict__ b_hh2,
    const float* __restrict__ w_fc,  const float* __restrict__ b_fc,
    float* __restrict__ out)
{
    __shared__ __align__(16) float h1s[BT][HP];
    __shared__ __align__(16) float h1rs[BT][HP];
    __shared__ __align__(16) float h2s[BT][HP];
    __shared__ __align__(16) float h2rs[BT][HP];
    __shared__ float g1s[200 * GP];
    __shared__ float g2as[200 * GP];
    __shared__ float g2bs[200 * GP];
    __shared__ __align__(16) float xs[2][BT][IND];
    __shared__ __align__(16) float wfcs[HP];
    __shared__ float bfcs;

    const int tid = threadIdx.x;
    const int B0  = blockIdx.x * BT;

    // ---- init shared state to zero (includes pads) ----
    for (int i = tid; i < BT * HP; i += NTHR) {
        ((float*)h1s)[i]  = 0.f; ((float*)h1rs)[i] = 0.f;
        ((float*)h2s)[i]  = 0.f; ((float*)h2rs)[i] = 0.f;
    }
    if (tid < HP)  wfcs[tid] = (tid < H) ? w_fc[tid] : 0.f;
    if (tid == 0)  bfcs = b_fc[0];
    if (tid < BT * IND) {                       // stage x(t=0)
        int b = tid >> 2, d = tid & 3;
        xs[0][b][d] = x[(B0 + b) * IND + d];
    }

    // ---- per-thread register weights (one gate row per thread) ----
    // G1  : tid [0,200)    -> w_hh1 row (wreg[0..49]) + w_ih1 row (wreg[52..55])
    // G2a : tid [224,424)  -> w_ih2 row
    // G2b : tid [448,648)  -> w_hh2 row
    float wreg[56];
    float breg = 0.f;
#pragma unroll
    for (int k = 0; k < 56; k++) wreg[k] = 0.f;

    if (tid < 200) {
        const int g = tid;
#pragma unroll
        for (int k = 0; k < H; k++) wreg[k] = w_hh1[g * H + k];
#pragma unroll
        for (int d = 0; d < IND; d++) wreg[52 + d] = w_ih1[g * IND + d];
        breg = b_ih1[g] + b_hh1[g];
    } else if (tid >= 224 && tid < 424) {
        const int g = tid - 224;
#pragma unroll
        for (int k = 0; k < H; k++) wreg[k] = w_ih2[g * H + k];
        breg = b_ih2[g] + b_hh2[g];
    } else if (tid >= 448 && tid < 648) {
        const int g = tid - 448;
#pragma unroll
        for (int k = 0; k < H; k++) wreg[k] = w_hh2[g * H + k];
    }

    // c-state registers (cell -> thread map is fixed across steps)
    float cst0 = 0.f, cst1 = 0.f, cst2 = 0.f;

    __syncthreads();

    // Pipeline: phase A(t): L1-gates(t) || L2-gates(t-1) || FC(t-2) || prefetch x(t+1)
    //           phase B(t): L1-update(t) || L2-update(t-1)
    for (int t = 0; t <= SEQ + 1; ++t) {
        // ================= phase A =================
        // Bands 200-223 and 424-447 are INTENTIONALLY IDLE: the guards below
        // must be exact, otherwise g = tid-224 / tid-448 goes negative and
        // stores corrupt the preceding gate buffer (the round-1/3 bug).
        if (tid < 200) {
            if (t < SEQ) {
                const int g   = tid;
                const int par = t & 1;
#pragma unroll 2
                for (int b = 0; b < BT; b++) {
                    float4 xv = *(const float4*)&xs[par][b][0];
                    float a0 = breg + wreg[52] * xv.x;
                    float a1 = wreg[53] * xv.y;
                    float a2 = wreg[54] * xv.z;
                    float a3 = wreg[55] * xv.w;
#pragma unroll
                    for (int q = 0; q < 13; q++) {
                        float4 hv = *(const float4*)&h1s[b][4 * q]; // broadcast
                        a0 += wreg[4 * q + 0] * hv.x;
                        a1 += wreg[4 * q + 1] * hv.y;
                        a2 += wreg[4 * q + 2] * hv.z;
                        a3 += wreg[4 * q + 3] * hv.w;
                    }
                    g1s[g * GP + b] = (a0 + a1) + (a2 + a3);
                }
            }
        } else if (tid >= 224 && tid < 424) {
            if (t >= 1 && t <= SEQ) {
                const int g = tid - 224;
#pragma unroll 2
                for (int b = 0; b < BT; b++) {
                    float a0 = breg, a1 = 0.f, a2 = 0.f, a3 = 0.f;
#pragma unroll
                    for (int q = 0; q < 13; q++) {
                        float4 hv = *(const float4*)&h1rs[b][4 * q]; // broadcast
                        a0 += wreg[4 * q + 0] * hv.x;
                        a1 += wreg[4 * q + 1] * hv.y;
                        a2 += wreg[4 * q + 2] * hv.z;
                        a3 += wreg[4 * q + 3] * hv.w;
                    }
                    g2as[g * GP + b] = (a0 + a1) + (a2 + a3);
                }
            }
        } else if (tid >= 448 && tid < 648) {
            if (t >= 1 && t <= SEQ) {
                const int g = tid - 448;
#pragma unroll 2
                for (int b = 0; b < BT; b++) {
                    float a0 = 0.f, a1 = 0.f, a2 = 0.f, a3 = 0.f;
#pragma unroll
                    for (int q = 0; q < 13; q++) {
                        float4 hv = *(const float4*)&h2s[b][4 * q]; // broadcast
                        a0 += wreg[4 * q + 0] * hv.x;
                        a1 += wreg[4 * q + 1] * hv.y;
                        a2 += wreg[4 * q + 2] * hv.z;
                        a3 += wreg[4 * q + 3] * hv.w;
                    }
                    g2bs[g * GP + b] = (a0 + a1) + (a2 + a3);
                }
            }
        } else if (tid >= 648 && tid < 664) {
            if (t >= 2) {                       // FC for step t-2
                const int b = tid - 648;
                float a0 = bfcs, a1 = 0.f, a2 = 0.f, a3 = 0.f;
#pragma unroll
                for (int q = 0; q < 13; q++) {
                    float4 wv = *(const float4*)&wfcs[4 * q];
                    float4 hv = *(const float4*)&h2rs[b][4 * q];
                    a0 += wv.x * hv.x; a1 += wv.y * hv.y;
                    a2 += wv.z * hv.z; a3 += wv.w * hv.w;
                }
                out[(t - 2) * BATCH + B0 + b] = (a0 + a1) + (a2 + a3);
            }
        } else if (tid >= 664) {
            if (t + 1 < SEQ) {                  // prefetch x(t+1)
                const int i = tid - 664;        // 0..7
#pragma unroll
                for (int j = 0; j < 8; j++) {
                    int idx = i * 8 + j;
                    int b = idx >> 2, d = idx & 3;
                    xs[(t + 1) & 1][b][d] =
                        x[((t + 1) * BATCH + B0 + b) * IND + d];
                }
            }
        }
        __syncthreads();

        // ================= phase B =================
        // 1600 cells: c<800 -> layer1 step t ; c>=800 -> layer2 step t-1
#define CELL_UPDATE(JC, CREG)                                              \
        {                                                                  \
            const int c = tid + (JC) * NTHR;                               \
            if (c < 1600) {                                                \
                const bool l2 = (c >= 800);                                \
                const int  r  = l2 ? c - 800 : c;                          \
                const int  u  = r >> 4;                                    \
                const int  b  = r & 15;                                    \
                const bool act = l2 ? (t >= 1 && t <= SEQ) : (t < SEQ);    \
                if (act) {                                                 \
                    float gi, gf, gg, go;                                  \
                    if (!l2) {                                             \
                        gi = g1s[(      u) * GP + b];                      \
                        gf = g1s[(H   + u) * GP + b];                      \
                        gg = g1s[(2*H + u) * GP + b];                      \
                        go = g1s[(3*H + u) * GP + b];                      \
                    } else {                                               \
                        gi = g2as[(      u) * GP + b] + g2bs[(      u) * GP + b]; \
                        gf = g2as[(H   + u) * GP + b] + g2bs[(H   + u) * GP + b]; \
                        gg = g2as[(2*H + u) * GP + b] + g2bs[(2*H + u) * GP + b]; \
                        go = g2as[(3*H + u) * GP + b] + g2bs[(3*H + u) * GP + b]; \
                    }                                                      \
                    float cn = sigf(gf) * (CREG) + sigf(gi) * tanh_acc(gg); \
                    (CREG) = cn;                                           \
                    float hv = sigf(go) * tanh_acc(cn);                    \
                    if (!l2) { h1s[b][u] = hv; h1rs[b][u] = fmaxf(hv, 0.f); } \
                    else     { h2s[b][u] = hv; h2rs[b][u] = fmaxf(hv, 0.f); } \
                }                                                          \
            }                                                              \
        }
        CELL_UPDATE(0, cst0)
        CELL_UPDATE(1, cst1)
        CELL_UPDATE(2, cst2)
#undef CELL_UPDATE
        __syncthreads();
    }
}

extern "C" void kernel_launch(void* const* d_in, const int* in_sizes, int n_in,
                              void* d_out, int out_size)
{
    const float* x     = (const float*)d_in[0];
    const float* w_ih1 = (const float*)d_in[1];
    const float* w_hh1 = (const float*)d_in[2];
    const float* b_ih1 = (const float*)d_in[3];
    const float* b_hh1 = (const float*)d_in[4];
    const float* w_ih2 = (const float*)d_in[5];
    const float* w_hh2 = (const float*)d_in[6];
    const float* b_ih2 = (const float*)d_in[7];
    const float* b_hh2 = (const float*)d_in[8];
    const float* w_fc  = (const float*)d_in[9];
    const float* b_fc  = (const float*)d_in[10];
    float* out = (float*)d_out;

    lstm_fused_kernel<<<NCTA, NTHR>>>(x, w_ih1, w_hh1, b_ih1, b_hh1,
                                      w_ih2, w_hh2, b_ih2, b_hh2,
                                      w_fc, b_fc, out);
}

// round 5
// speedup vs baseline: 1.2095x; 1.2095x over previous
#include <cuda_runtime.h>

#define SEQ   512
#define BATCH 2048
#define IND   4
#define H     50
#define BT    16                 // batch tile per CTA
#define NCTA  (BATCH / BT)       // 128
#define NTHR  672                // 21 warps
#define HP    52                 // padded hidden (even, mult of 4)
#define GP    17                 // gates row pad (conflict-free)

typedef unsigned long long ull;

// ---- packed dual-fp32 helpers (sm_103a FFMA2 path; ptxas never emits this
//      from C++, only via explicit PTX fma.rn.f32x2) ----
__device__ __forceinline__ ull pack2(float lo, float hi) {
    ull r; asm("mov.b64 %0, {%1, %2};" : "=l"(r) : "f"(lo), "f"(hi)); return r;
}
__device__ __forceinline__ void unpack2(ull v, float& lo, float& hi) {
    asm("mov.b64 {%0, %1}, %2;" : "=f"(lo), "=f"(hi) : "l"(v));
}
__device__ __forceinline__ void fma2(ull& d, ull a, ull b) {
    asm("fma.rn.f32x2 %0, %1, %2, %0;" : "+l"(d) : "l"(a), "l"(b));
}

// ---- fast activations: recurrence amplification measured at ~2x, so
//      MUFU-based fast math keeps final rel_err ~1e-5 (gate is 1e-3) ----
__device__ __forceinline__ float sigf(float x) {
    return __fdividef(1.0f, 1.0f + __expf(-x));
}
__device__ __forceinline__ float tanh_fast(float x) {
    float ax = fabsf(x);
    float e  = __expf(-2.0f * ax);               // in (0,1], no overflow
    float t  = __fdividef(1.0f - e, 1.0f + e);   // no cancellation blowup
    return copysignf(t, x);
}

__global__ __launch_bounds__(NTHR, 1)
void lstm_fused_kernel(
    const float* __restrict__ x,
    const float* __restrict__ w_ih1, const float* __restrict__ w_hh1,
    const float* __restrict__ b_ih1, const float* __restrict__ b_hh1,
    const float* __restrict__ w_ih2, const float* __restrict__ w_hh2,
    const float* __restrict__ b_ih2, const float* __restrict__ b_hh2,
    const float* __restrict__ w_fc,  const float* __restrict__ b_fc,
    float* __restrict__ out)
{
    __shared__ __align__(16) float h1s[BT][HP];
    __shared__ __align__(16) float h1rs[BT][HP];
    __shared__ __align__(16) float h2s[BT][HP];
    __shared__ __align__(16) float h2rs[BT][HP];
    __shared__ float g1s[200 * GP];
    __shared__ float g2as[200 * GP];
    __shared__ float g2bs[200 * GP];
    __shared__ __align__(16) float xs[2][BT][IND];
    __shared__ __align__(16) float wfcs[HP];
    __shared__ float bfcs;

    const int tid = threadIdx.x;
    const int B0  = blockIdx.x * BT;

    // ---- init shared state to zero (includes pads) ----
    for (int i = tid; i < BT * HP; i += NTHR) {
        ((float*)h1s)[i]  = 0.f; ((float*)h1rs)[i] = 0.f;
        ((float*)h2s)[i]  = 0.f; ((float*)h2rs)[i] = 0.f;
    }
    if (tid < HP)  wfcs[tid] = (tid < H) ? w_fc[tid] : 0.f;
    if (tid == 0)  bfcs = b_fc[0];
    if (tid < BT * IND) {                       // stage x(t=0)
        int b = tid >> 2, d = tid & 3;
        xs[0][b][d] = x[(B0 + b) * IND + d];
    }

    // ---- per-thread packed register weights (one gate row per thread) ----
    // G1  : tid [0,200)    -> w_hh1 row (25 pairs) + w_ih1 row (2 pairs)
    // G2a : tid [224,424)  -> w_ih2 row (25 pairs)
    // G2b : tid [448,648)  -> w_hh2 row (25 pairs)
    ull  w2[25];
    ull  wx2[2];
    float breg = 0.f;
#pragma unroll
    for (int q = 0; q < 25; q++) w2[q] = 0ULL;
    wx2[0] = wx2[1] = 0ULL;

    if (tid < 200) {
        const int g = tid;
#pragma unroll
        for (int q = 0; q < 25; q++)
            w2[q] = pack2(w_hh1[g * H + 2 * q], w_hh1[g * H + 2 * q + 1]);
        wx2[0] = pack2(w_ih1[g * IND + 0], w_ih1[g * IND + 1]);
        wx2[1] = pack2(w_ih1[g * IND + 2], w_ih1[g * IND + 3]);
        breg = b_ih1[g] + b_hh1[g];
    } else if (tid >= 224 && tid < 424) {
        const int g = tid - 224;
#pragma unroll
        for (int q = 0; q < 25; q++)
            w2[q] = pack2(w_ih2[g * H + 2 * q], w_ih2[g * H + 2 * q + 1]);
        breg = b_ih2[g] + b_hh2[g];
    } else if (tid >= 448 && tid < 648) {
        const int g = tid - 448;
#pragma unroll
        for (int q = 0; q < 25; q++)
            w2[q] = pack2(w_hh2[g * H + 2 * q], w_hh2[g * H + 2 * q + 1]);
    }

    // c-state registers (cell -> thread map fixed across steps)
    float cst0 = 0.f, cst1 = 0.f, cst2 = 0.f;

    __syncthreads();

    // Pipeline: phase A(t): L1-gates(t) || L2-gates(t-1) || FC(t-2) || prefetch x(t+1)
    //           phase B(t): L1-update(t) || L2-update(t-1)
    for (int t = 0; t <= SEQ + 1; ++t) {
        // ================= phase A =================
        // Bands 200-223 / 424-447 intentionally idle; guards must be exact.
        if (tid < 200) {
            if (t < SEQ) {
                const int g   = tid;
                const int par = t & 1;
#pragma unroll 2
                for (int b = 0; b < BT; b++) {
                    const ull* hp = (const ull*)&h1s[b][0];   // 25 pairs, broadcast
                    const ull* xp = (const ull*)&xs[par][b][0];
                    ull accA = 0ULL, accB = 0ULL;             // 2 chains
#pragma unroll
                    for (int q = 0; q < 24; q += 2) {
                        fma2(accA, w2[q],     hp[q]);
                        fma2(accB, w2[q + 1], hp[q + 1]);
                    }
                    fma2(accA, w2[24], hp[24]);
                    fma2(accA, wx2[0], xp[0]);
                    fma2(accB, wx2[1], xp[1]);
                    float a0, a1, b0, b1;
                    unpack2(accA, a0, a1);
                    unpack2(accB, b0, b1);
                    g1s[g * GP + b] = breg + ((a0 + a1) + (b0 + b1));
                }
            }
        } else if (tid >= 224 && tid < 424) {
            if (t >= 1 && t <= SEQ) {
                const int g = tid - 224;
#pragma unroll 2
                for (int b = 0; b < BT; b++) {
                    const ull* hp = (const ull*)&h1rs[b][0];
                    ull accA = 0ULL, accB = 0ULL;
#pragma unroll
                    for (int q = 0; q < 24; q += 2) {
                        fma2(accA, w2[q],     hp[q]);
                        fma2(accB, w2[q + 1], hp[q + 1]);
                    }
                    fma2(accA, w2[24], hp[24]);
                    float a0, a1, b0, b1;
                    unpack2(accA, a0, a1);
                    unpack2(accB, b0, b1);
                    g2as[g * GP + b] = breg + ((a0 + a1) + (b0 + b1));
                }
            }
        } else if (tid >= 448 && tid < 648) {
            if (t >= 1 && t <= SEQ) {
                const int g = tid - 448;
#pragma unroll 2
                for (int b = 0; b < BT; b++) {
                    const ull* hp = (const ull*)&h2s[b][0];
                    ull accA = 0ULL, accB = 0ULL;
#pragma unroll
                    for (int q = 0; q < 24; q += 2) {
                        fma2(accA, w2[q],     hp[q]);
                        fma2(accB, w2[q + 1], hp[q + 1]);
                    }
                    fma2(accA, w2[24], hp[24]);
                    float a0, a1, b0, b1;
                    unpack2(accA, a0, a1);
                    unpack2(accB, b0, b1);
                    g2bs[g * GP + b] = (a0 + a1) + (b0 + b1);
                }
            }
        } else if (tid >= 648 && tid < 664) {
            if (t >= 2) {                       // FC for step t-2
                const int b = tid - 648;
                float a0 = bfcs, a1 = 0.f, a2 = 0.f, a3 = 0.f;
#pragma unroll
                for (int q = 0; q < 13; q++) {
                    float4 wv = *(const float4*)&wfcs[4 * q];
                    float4 hv = *(const float4*)&h2rs[b][4 * q];
                    a0 += wv.x * hv.x; a1 += wv.y * hv.y;
                    a2 += wv.z * hv.z; a3 += wv.w * hv.w;
                }
                out[(t - 2) * BATCH + B0 + b] = (a0 + a1) + (a2 + a3);
            }
        } else if (tid >= 664) {
            if (t + 1 < SEQ) {                  // prefetch x(t+1)
                const int i = tid - 664;        // 0..7
#pragma unroll
                for (int j = 0; j < 8; j++) {
                    int idx = i * 8 + j;
                    int b = idx >> 2, d = idx & 3;
                    xs[(t + 1) & 1][b][d] =
                        x[((t + 1) * BATCH + B0 + b) * IND + d];
                }
            }
        }
        __syncthreads();

        // ================= phase B =================
        // 1600 cells: c<800 -> layer1 step t ; c>=800 -> layer2 step t-1
#define CELL_UPDATE(JC, CREG)                                              \
        {                                                                  \
            const int c = tid + (JC) * NTHR;                               \
            if (c < 1600) {                                                \
                const bool l2 = (c >= 800);                                \
                const int  r  = l2 ? c - 800 : c;                          \
                const int  u  = r >> 4;                                    \
                const int  b  = r & 15;                                    \
                const bool act = l2 ? (t >= 1 && t <= SEQ) : (t < SEQ);    \
                if (act) {                                                 \
                    float gi, gf, gg, go;                                  \
                    if (!l2) {                                             \
                        gi = g1s[(      u) * GP + b];                      \
                        gf = g1s[(H   + u) * GP + b];                      \
                        gg = g1s[(2*H + u) * GP + b];                      \
                        go = g1s[(3*H + u) * GP + b];                      \
                    } else {                                               \
                        gi = g2as[(      u) * GP + b] + g2bs[(      u) * GP + b]; \
                        gf = g2as[(H   + u) * GP + b] + g2bs[(H   + u) * GP + b]; \
                        gg = g2as[(2*H + u) * GP + b] + g2bs[(2*H + u) * GP + b]; \
                        go = g2as[(3*H + u) * GP + b] + g2bs[(3*H + u) * GP + b]; \
                    }                                                      \
                    float cn = sigf(gf) * (CREG) + sigf(gi) * tanh_fast(gg); \
                    (CREG) = cn;                                           \
                    float hv = sigf(go) * tanh_fast(cn);                   \
                    if (!l2) { h1s[b][u] = hv; h1rs[b][u] = fmaxf(hv, 0.f); } \
                    else     { h2s[b][u] = hv; h2rs[b][u] = fmaxf(hv, 0.f); } \
                }                                                          \
            }                                                              \
        }
        CELL_UPDATE(0, cst0)
        CELL_UPDATE(1, cst1)
        CELL_UPDATE(2, cst2)
#undef CELL_UPDATE
        __syncthreads();
    }
}

extern "C" void kernel_launch(void* const* d_in, const int* in_sizes, int n_in,
                              void* d_out, int out_size)
{
    const float* x     = (const float*)d_in[0];
    const float* w_ih1 = (const float*)d_in[1];
    const float* w_hh1 = (const float*)d_in[2];
    const float* b_ih1 = (const float*)d_in[3];
    const float* b_hh1 = (const float*)d_in[4];
    const float* w_ih2 = (const float*)d_in[5];
    const float* w_hh2 = (const float*)d_in[6];
    const float* b_ih2 = (const float*)d_in[7];
    const float* b_hh2 = (const float*)d_in[8];
    const float* w_fc  = (const float*)d_in[9];
    const float* b_fc  = (const float*)d_in[10];
    float* out = (float*)d_out;

    lstm_fused_kernel<<<NCTA, NTHR>>>(x, w_ih1, w_hh1, b_ih1, b_hh1,
                                      w_ih2, w_hh2, b_ih2, b_hh2,
                                      w_fc, b_fc, out);
}